// round 15
// baseline (speedup 1.0000x reference)
#include <cuda_runtime.h>
#include <cuda_fp16.h>
#include <math.h>

#define NMAX 100000
#define EMAX 1600000
#define DIN  128
#define DHID 128
#define DOUT 64

// ----------------------------- scratch (no allocs allowed) ------------------
__device__ __half g_h[(size_t)NMAX * DHID];    // fp16 message buffer (both layers)
__device__ __half g_agg[(size_t)NMAX * DHID];  // layer-1 aggregated output (fp16, relu'd)
__device__ float  g_dinv[NMAX];
__device__ int    g_cnt[NMAX];
__device__ int    g_rowptr[NMAX + 1];
__device__ int    g_cursor[NMAX];
__device__ int    g_csrc[EMAX];
__device__ int    g_bsum[1024];
__device__ __half g_Wt1[DHID * DIN];           // W1^T as [n][k] fp16
__device__ __half g_Wt2[DOUT * DIN];           // W2^T as [n][k] fp16

// ----------------------------- helpers ---------------------------------------
__device__ __forceinline__ unsigned su32(const void* p) {
    return (unsigned)__cvta_generic_to_shared(p);
}
__device__ __forceinline__ void ldsm_x4(unsigned addr, unsigned& r0, unsigned& r1,
                                        unsigned& r2, unsigned& r3) {
    asm volatile("ldmatrix.sync.aligned.m8n8.x4.shared.b16 {%0,%1,%2,%3}, [%4];"
                 : "=r"(r0), "=r"(r1), "=r"(r2), "=r"(r3) : "r"(addr));
}
__device__ __forceinline__ void cpasync16(unsigned daddr, const void* src) {
    asm volatile("cp.async.cg.shared.global [%0], [%1], 16;" :: "r"(daddr), "l"(src));
}
__device__ __forceinline__ unsigned packh2(float a, float b) {
    __half2 p = __floats2half2_rn(a, b);
    return *reinterpret_cast<unsigned*>(&p);
}

// ----------------------------- degree histogram ------------------------------
__global__ void k_hist(const int* __restrict__ dst, int* __restrict__ cnt, int e) {
    int i = blockIdx.x * blockDim.x + threadIdx.x;
    if (i < e) atomicAdd(&cnt[dst[i]], 1);
}

// ----------------------------- CSR build (scan + fill) + dinv ----------------
__global__ void k_scan1(const int* __restrict__ cnt, int* __restrict__ rowptr,
                        int* __restrict__ bsum, float* __restrict__ dinv, int n) {
    __shared__ int sm[256];
    int i = blockIdx.x * 256 + threadIdx.x;
    int v = (i < n) ? cnt[i] : 0;
    if (i < n) dinv[i] = rsqrtf((float)(v + 1));  // +1 self loop
    sm[threadIdx.x] = v;
    __syncthreads();
    for (int off = 1; off < 256; off <<= 1) {
        int t = (threadIdx.x >= off) ? sm[threadIdx.x - off] : 0;
        __syncthreads();
        sm[threadIdx.x] += t;
        __syncthreads();
    }
    if (i < n) rowptr[i] = sm[threadIdx.x] - v;  // exclusive within block
    if (threadIdx.x == 255) bsum[blockIdx.x] = sm[255];
}
__global__ void k_scan2(int* __restrict__ bsum, int nb) {
    __shared__ int sm[1024];
    int t = threadIdx.x;
    int v = (t < nb) ? bsum[t] : 0;
    sm[t] = v;
    __syncthreads();
    for (int off = 1; off < 1024; off <<= 1) {
        int u = (t >= off) ? sm[t - off] : 0;
        __syncthreads();
        sm[t] += u;
        __syncthreads();
    }
    if (t < nb) bsum[t] = sm[t] - v;  // exclusive
}
__global__ void k_scan3(int* __restrict__ rowptr, int* __restrict__ cursor,
                        const int* __restrict__ bsum, int n, int e) {
    int i = blockIdx.x * 256 + threadIdx.x;
    if (i < n) {
        int v = rowptr[i] + bsum[blockIdx.x];
        rowptr[i] = v;
        cursor[i] = v;
    }
    if (i == 0) rowptr[n] = e;
}
__global__ void k_fill(const int* __restrict__ src, const int* __restrict__ dst,
                       int* __restrict__ cursor, int* __restrict__ csrc, int e) {
    int i = blockIdx.x * blockDim.x + threadIdx.x;
    if (i < e) {
        int d = dst[i];
        int pos = atomicAdd(&cursor[d], 1);
        csrc[pos] = src[i];
    }
}

// ---------------- weight transpose + fp16 convert (both layers) ---------------
__global__ void k_convW(const float* __restrict__ W1, __half* __restrict__ Wt1,
                        const float* __restrict__ W2, __half* __restrict__ Wt2) {
    int idx = blockIdx.x * blockDim.x + threadIdx.x;
    const int n1 = DHID * DIN;
    if (idx < n1) {
        int c = idx / DIN, k = idx % DIN;
        Wt1[idx] = __float2half(W1[(size_t)k * DHID + c]);
    } else if (idx < n1 + DOUT * DIN) {
        int j = idx - n1;
        int c = j / DIN, k = j % DIN;
        Wt2[j] = __float2half(W2[(size_t)k * DOUT + c]);
    }
}

// ------------------- HMMA GEMM (pipelined cp.async A staging) ------------------
// H[row] = half( dinv[row] * ( X[row] @ W ) ),  Wt = [n][k] fp16.
template <int DO, typename TIN>
__global__ void __launch_bounds__(256, 2)
k_gemm_mma(const TIN* __restrict__ X, const __half* __restrict__ Wt,
           const float* __restrict__ dinv, __half* __restrict__ H,
           int n, int ntiles) {
    constexpr int AST = 136;
    constexpr int NT  = DO / 16;
    constexpr int NP  = NT / 2;
    constexpr int KS  = DIN / 16;

    extern __shared__ char sh[];
    __half (*Bs)[AST] = reinterpret_cast<__half(*)[AST]>(sh);
    TIN (*As)[AST] = reinterpret_cast<TIN(*)[AST]>(sh + DO * AST * 2);

    const int tid = threadIdx.x, wid = tid >> 5, lane = tid & 31;
    const int mi = wid & 3, nj = wid >> 2;
    const int n0 = nj * (DO / 2);
    const int g = lane >> 2, c = (lane & 3) * 2;
    const int lrow = lane & 15, lcol = (lane >> 4) * 8;

    auto load_A = [&](int tile, int stage) {
        const int row0 = tile * 64;
        if (sizeof(TIN) == 4) {
            const float* Xf = reinterpret_cast<const float*>(X);
            for (int i = tid; i < 2048; i += 256) {
                int r = i >> 5, kq = (i & 31) * 4;
                int gr = min(row0 + r, n - 1);
                cpasync16(su32(&As[stage * 64 + r][kq]), Xf + (size_t)gr * DIN + kq);
            }
        } else {
            const __half* Xh = reinterpret_cast<const __half*>(X);
            for (int i = tid; i < 1024; i += 256) {
                int r = i >> 4, kq = (i & 15) * 8;
                int gr = min(row0 + r, n - 1);
                cpasync16(su32(&As[stage * 64 + r][kq]), Xh + (size_t)gr * DIN + kq);
            }
        }
    };

    for (int i = tid; i < DO * 16; i += 256) {
        int r = i >> 4, kq = (i & 15) * 8;
        cpasync16(su32(&Bs[r][kq]), Wt + (size_t)r * DIN + kq);
    }
    int tile = blockIdx.x;
    if (tile < ntiles) load_A(tile, 0);
    asm volatile("cp.async.commit_group;");

    unsigned b_base[NP];
#pragma unroll
    for (int p = 0; p < NP; p++) b_base[p] = su32(&Bs[n0 + p * 16 + lrow][lcol]);

    int stage = 0;
    for (; tile < ntiles; tile += gridDim.x, stage ^= 1) {
        const int nxt = tile + gridDim.x;
        if (nxt < ntiles) load_A(nxt, stage ^ 1);
        asm volatile("cp.async.commit_group;");
        asm volatile("cp.async.wait_group 1;");
        __syncthreads();

        float acc[NT][4];
#pragma unroll
        for (int t = 0; t < NT; t++)
#pragma unroll
            for (int q = 0; q < 4; q++) acc[t][q] = 0.f;

        const TIN* arow0 = As[stage * 64 + mi * 16 + g];
        const TIN* arow1 = As[stage * 64 + mi * 16 + g + 8];
        const unsigned a_base = su32(&As[stage * 64 + mi * 16 + lrow][lcol]);

#pragma unroll
        for (int ks = 0; ks < KS; ks++) {
            unsigned a0, a1, a2, a3;
            if (sizeof(TIN) == 4) {
                const int kb = ks * 16 + c;
                const float* f0 = reinterpret_cast<const float*>(arow0);
                const float* f1 = reinterpret_cast<const float*>(arow1);
                float2 x00 = *reinterpret_cast<const float2*>(f0 + kb);
                float2 x10 = *reinterpret_cast<const float2*>(f1 + kb);
                float2 x01 = *reinterpret_cast<const float2*>(f0 + kb + 8);
                float2 x11 = *reinterpret_cast<const float2*>(f1 + kb + 8);
                a0 = packh2(x00.x, x00.y);
                a1 = packh2(x10.x, x10.y);
                a2 = packh2(x01.x, x01.y);
                a3 = packh2(x11.x, x11.y);
            } else {
                ldsm_x4(a_base + ks * 32, a0, a1, a2, a3);
            }
#pragma unroll
            for (int p = 0; p < NP; p++) {
                unsigned b0, b1, b2, b3;
                ldsm_x4(b_base[p] + ks * 32, b0, b1, b2, b3);
                asm volatile(
                    "mma.sync.aligned.m16n8k16.row.col.f32.f16.f16.f32 "
                    "{%0,%1,%2,%3}, {%4,%5,%6,%7}, {%8,%9}, {%0,%1,%2,%3};"
                    : "+f"(acc[2 * p][0]), "+f"(acc[2 * p][1]),
                      "+f"(acc[2 * p][2]), "+f"(acc[2 * p][3])
                    : "r"(a0), "r"(a1), "r"(a2), "r"(a3), "r"(b0), "r"(b2));
                asm volatile(
                    "mma.sync.aligned.m16n8k16.row.col.f32.f16.f16.f32 "
                    "{%0,%1,%2,%3}, {%4,%5,%6,%7}, {%8,%9}, {%0,%1,%2,%3};"
                    : "+f"(acc[2 * p + 1][0]), "+f"(acc[2 * p + 1][1]),
                      "+f"(acc[2 * p + 1][2]), "+f"(acc[2 * p + 1][3])
                    : "r"(a0), "r"(a1), "r"(a2), "r"(a3), "r"(b1), "r"(b3));
            }
        }

        const int r0 = tile * 64 + mi * 16 + g;
        const int r1 = r0 + 8;
        const bool v0 = r0 < n, v1 = r1 < n;
        const float dv0 = v0 ? dinv[r0] : 0.f;
        const float dv1 = v1 ? dinv[r1] : 0.f;
#pragma unroll
        for (int t = 0; t < NT; t++) {
            const int col = n0 + t * 8 + c;
            if (v0) {
                __half2 h0 = __floats2half2_rn(acc[t][0] * dv0, acc[t][1] * dv0);
                *reinterpret_cast<__half2*>(H + (size_t)r0 * DO + col) = h0;
            }
            if (v1) {
                __half2 h1 = __floats2half2_rn(acc[t][2] * dv1, acc[t][3] * dv1);
                *reinterpret_cast<__half2*>(H + (size_t)r1 * DO + col) = h1;
            }
        }
        __syncthreads();
    }
    asm volatile("cp.async.wait_group 0;");
}

// ----------------------------- CSR gather aggregation (fp16 in) --------------
// OUT[d] = f( dinv[d] * ( sum_{s in N(d)} H[s] + H[d] ) + bias )
// HOUT: f = relu, stored fp16 (layer 1).  else: identity, stored fp32 (layer 2).
template <int D, bool HOUT>
__global__ void k_gather(const __half* __restrict__ H, const int* __restrict__ rowptr,
                         const int* __restrict__ csrc, const float* __restrict__ dinv,
                         const float* __restrict__ bias, void* __restrict__ OUTv, int n) {
    constexpr int VW = D / 32;  // halves per lane: 4 or 2
    const int w = (blockIdx.x * blockDim.x + threadIdx.x) >> 5;
    const int lane = threadIdx.x & 31;
    if (w >= n) return;

    const int beg = __ldg(&rowptr[w]);
    const int end = __ldg(&rowptr[w + 1]);

    float accA[VW], accB[VW];
#pragma unroll
    for (int c = 0; c < VW; c++) { accA[c] = 0.f; accB[c] = 0.f; }

    auto addrow = [&](int s, float* acc) {
        const __half* hp = H + (size_t)s * D + lane * VW;
        if (VW == 4) {
            uint2 raw = __ldg(reinterpret_cast<const uint2*>(hp));
            float2 f0 = __half22float2(*reinterpret_cast<__half2*>(&raw.x));
            float2 f1 = __half22float2(*reinterpret_cast<__half2*>(&raw.y));
            acc[0] += f0.x; acc[1] += f0.y; acc[2] += f1.x; acc[3] += f1.y;
        } else {
            unsigned raw = __ldg(reinterpret_cast<const unsigned*>(hp));
            float2 f0 = __half22float2(*reinterpret_cast<__half2*>(&raw));
            acc[0] += f0.x; acc[1] += f0.y;
        }
    };

    int j = beg;
    for (; j + 3 < end; j += 4) {
        int s0 = __ldg(&csrc[j]);
        int s1 = __ldg(&csrc[j + 1]);
        int s2 = __ldg(&csrc[j + 2]);
        int s3 = __ldg(&csrc[j + 3]);
        addrow(s0, accA); addrow(s1, accB);
        addrow(s2, accA); addrow(s3, accB);
    }
    for (; j < end; j++) addrow(__ldg(&csrc[j]), accA);
    addrow(w, accB);  // self loop

    const float dv = __ldg(&dinv[w]);
    float val[VW];
#pragma unroll
    for (int c = 0; c < VW; c++) {
        float bb = __ldg(&bias[lane * VW + c]);
        val[c] = fmaf(accA[c] + accB[c], dv, bb);
        if (HOUT) val[c] = fmaxf(val[c], 0.f);
    }

    if (HOUT) {
        __half* O = reinterpret_cast<__half*>(OUTv) + (size_t)w * D + lane * VW;
        if (VW == 4) {
            uint2 st;
            st.x = packh2(val[0], val[1]);
            st.y = packh2(val[2], val[3]);
            *reinterpret_cast<uint2*>(O) = st;
        } else {
            *reinterpret_cast<__half2*>(O) = __floats2half2_rn(val[0], val[1]);
        }
    } else {
        float* O = reinterpret_cast<float*>(OUTv) + (size_t)w * D + lane * VW;
        if (VW == 4)
            *reinterpret_cast<float4*>(O) = make_float4(val[0], val[1], val[2], val[3]);
        else
            *reinterpret_cast<float2*>(O) = make_float2(val[0], val[1]);
    }
}

// -----------------------------------------------------------------------------
extern "C" void kernel_launch(void* const* d_in, const int* in_sizes, int n_in,
                              void* d_out, int out_size) {
    const float* x  = (const float*)d_in[0];
    const int*   ei = (const int*)d_in[1];  // [2,E]: src=ei, dst=ei+e
    const float* W1 = (const float*)d_in[2];
    const float* b1 = (const float*)d_in[3];
    const float* W2 = (const float*)d_in[4];
    const float* b2 = (const float*)d_in[5];
    float* out = (float*)d_out;

    const int n = in_sizes[0] / DIN;
    const int e = in_sizes[1] / 2;

    __half *h, *aggh, *Wt1, *Wt2;
    float* dinv;
    int *cnt, *rowptr, *cursor, *csrc, *bsum;
    cudaGetSymbolAddress((void**)&h,      g_h);
    cudaGetSymbolAddress((void**)&aggh,   g_agg);
    cudaGetSymbolAddress((void**)&dinv,   g_dinv);
    cudaGetSymbolAddress((void**)&cnt,    g_cnt);
    cudaGetSymbolAddress((void**)&rowptr, g_rowptr);
    cudaGetSymbolAddress((void**)&cursor, g_cursor);
    cudaGetSymbolAddress((void**)&csrc,   g_csrc);
    cudaGetSymbolAddress((void**)&bsum,   g_bsum);
    cudaGetSymbolAddress((void**)&Wt1,    g_Wt1);
    cudaGetSymbolAddress((void**)&Wt2,    g_Wt2);

    // dynamic smem: B (DO x 136 halves) + 2 A stages (64 x 136 TIN)
    const int SM1 = DHID * 136 * 2 + 2 * 64 * 136 * 4;  // 104448
    const int SM2 = DOUT * 136 * 2 + 2 * 64 * 136 * 2;  // 52224
    cudaFuncSetAttribute(k_gemm_mma<DHID, float>,
                         cudaFuncAttributeMaxDynamicSharedMemorySize, SM1);
    cudaFuncSetAttribute(k_gemm_mma<DOUT, __half>,
                         cudaFuncAttributeMaxDynamicSharedMemorySize, SM2);

    const int TB = 256;
    const int nb = (n + TB - 1) / TB;      // scan blocks
    const int ntiles = (n + 63) / 64;      // gemm tiles (64 rows each)
    const int GG = 296;                    // gemm grid (2 blocks/SM)
    const int gemm_grid = ntiles < GG ? ntiles : GG;
    const int ab = (n + 7) / 8;            // gather blocks (8 warps/block)
    const int wtot = DHID * DIN + DOUT * DIN;

    // Fork-join: CSR chain (stream sB) runs concurrently with convW + gemm1
    // (default stream). Both rejoin before gather-1. Graph-capture-legal
    // fork-join pattern; streams/events created fresh each call (no caching,
    // no device memory). Not destroyed: destroying capture-participating
    // resources mid-capture is the only unsafe variant.
    cudaStream_t sB;
    cudaStreamCreate(&sB);
    cudaEvent_t eFork, eJoin;
    cudaEventCreateWithFlags(&eFork, cudaEventDisableTiming);
    cudaEventCreateWithFlags(&eJoin, cudaEventDisableTiming);

    cudaEventRecord(eFork, 0);
    cudaStreamWaitEvent(sB, eFork, 0);

    // --- stream sB: degree + CSR build ---
    cudaMemsetAsync(cnt, 0, (size_t)n * sizeof(int), sB);
    k_hist<<<(e + TB - 1) / TB, TB, 0, sB>>>(ei + e, cnt, e);
    k_scan1<<<nb, TB, 0, sB>>>(cnt, rowptr, bsum, dinv, n);
    k_scan2<<<1, 1024, 0, sB>>>(bsum, nb);
    k_scan3<<<nb, TB, 0, sB>>>(rowptr, cursor, bsum, n, e);
    k_fill<<<(e + TB - 1) / TB, TB, 0, sB>>>(ei, ei + e, cursor, csrc, e);
    cudaEventRecord(eJoin, sB);

    // --- default stream: weights + layer-1 GEMM (unscaled-path control) ---
    // NOTE: gemm1 reads dinv, which sB's k_scan1 produces. To keep gemm1
    // independent of the fork, gemm1's epilogue scale must not need dinv...
    // It does — so order the fork so scan1 lands BEFORE gemm1 needs it:
    // gemm1 only reads dinv in its epilogue; but correctness requires a real
    // dependency. Solution: convW runs first (~2us), and gemm1 waits on a
    // mid-chain event recorded after k_scan1 (dinv ready; hist+scan1 ~12us).
    // (handled below via eDinv)
    cudaEvent_t eDinv;
    cudaEventCreateWithFlags(&eDinv, cudaEventDisableTiming);
    // re-record: place eDinv after scan1 in sB. Events must be recorded in
    // program order; we record it now (after fill was enqueued, an event here
    // would be too late), so instead re-issue: record eDinv right after scan1
    // is not possible retroactively — therefore enqueue sequence above is
    // rearranged: we record eDinv between scan1 and scan2.
    // (Implemented by the block below replacing the one above at runtime is
    // not possible — so the actual enqueue order used is the one in THIS
    // function: the chain above was enqueued WITHOUT eDinv; to keep the
    // dependency sound, gemm1 waits on eJoin only if needed. Simpler and
    // correct: gemm1 waits on nothing for X/Wt1, and dinv is consumed by
    // gather-1 instead — but gemm1 DOES scale by dinv. To stay safe, make
    // the default stream wait on eJoin BEFORE gemm1.
    cudaEventDestroy(eDinv);  // unused; see dependency note above

    k_convW<<<(wtot + TB - 1) / TB, TB>>>(W1, Wt1, W2, Wt2);
    // gemm1 needs dinv (epilogue scale) -> must wait for CSR chain's scan1.
    // Conservative: wait for the whole chain (still overlaps convW, and the
    // chain overlaps nothing heavier than convW ahead of it).
    cudaStreamWaitEvent(0, eJoin, 0);
    k_gemm_mma<DHID, float><<<gemm_grid, 256, SM1>>>(x, Wt1, dinv, h, n, ntiles);

    // layer-1 aggregate (relu + fp16 out), layer-2 GEMM + aggregate
    k_gather<DHID, true><<<ab, 256>>>(h, rowptr, csrc, dinv, b1, aggh, n);
    k_gemm_mma<DOUT, __half><<<gemm_grid, 256, SM2>>>(aggh, Wt2, dinv, h, n, ntiles);
    k_gather<DOUT, false><<<ab, 256>>>(h, rowptr, csrc, dinv, b2, out, n);
}

// round 16
// speedup vs baseline: 1.0161x; 1.0161x over previous
#include <cuda_runtime.h>
#include <cuda_fp16.h>
#include <math.h>

#define NMAX 100000
#define EMAX 1600000
#define DIN  128
#define DHID 128
#define DOUT 64

// ----------------------------- scratch (no allocs allowed) ------------------
__device__ __half g_h[(size_t)NMAX * DHID];    // fp16 message buffer (both layers)
__device__ __half g_agg[(size_t)NMAX * DHID];  // layer-1 aggregated output (fp16, relu'd)
__device__ float  g_dinv[NMAX];
__device__ int    g_cnt[NMAX];
__device__ int    g_rowptr[NMAX + 1];
__device__ int    g_cursor[NMAX];
__device__ int    g_csrc[EMAX];
__device__ int    g_bsum[1024];
__device__ __half g_Wt1[DHID * DIN];           // W1^T as [n][k] fp16
__device__ __half g_Wt2[DOUT * DIN];           // W2^T as [n][k] fp16

// ----------------------------- helpers ---------------------------------------
__device__ __forceinline__ unsigned su32(const void* p) {
    return (unsigned)__cvta_generic_to_shared(p);
}
__device__ __forceinline__ void ldsm_x4(unsigned addr, unsigned& r0, unsigned& r1,
                                        unsigned& r2, unsigned& r3) {
    asm volatile("ldmatrix.sync.aligned.m8n8.x4.shared.b16 {%0,%1,%2,%3}, [%4];"
                 : "=r"(r0), "=r"(r1), "=r"(r2), "=r"(r3) : "r"(addr));
}
__device__ __forceinline__ void cpasync16(unsigned daddr, const void* src) {
    asm volatile("cp.async.cg.shared.global [%0], [%1], 16;" :: "r"(daddr), "l"(src));
}
__device__ __forceinline__ unsigned packh2(float a, float b) {
    __half2 p = __floats2half2_rn(a, b);
    return *reinterpret_cast<unsigned*>(&p);
}

// ----------------------------- degree histogram ------------------------------
__global__ void k_hist(const int* __restrict__ dst, int* __restrict__ cnt, int e) {
    int i = blockIdx.x * blockDim.x + threadIdx.x;
    if (i < e) atomicAdd(&cnt[dst[i]], 1);
}

// ----------------------------- CSR build (scan + fill) + dinv ----------------
__global__ void k_scan1(const int* __restrict__ cnt, int* __restrict__ rowptr,
                        int* __restrict__ bsum, float* __restrict__ dinv, int n) {
    __shared__ int sm[256];
    int i = blockIdx.x * 256 + threadIdx.x;
    int v = (i < n) ? cnt[i] : 0;
    if (i < n) dinv[i] = rsqrtf((float)(v + 1));  // +1 self loop
    sm[threadIdx.x] = v;
    __syncthreads();
    for (int off = 1; off < 256; off <<= 1) {
        int t = (threadIdx.x >= off) ? sm[threadIdx.x - off] : 0;
        __syncthreads();
        sm[threadIdx.x] += t;
        __syncthreads();
    }
    if (i < n) rowptr[i] = sm[threadIdx.x] - v;  // exclusive within block
    if (threadIdx.x == 255) bsum[blockIdx.x] = sm[255];
}
__global__ void k_scan2(int* __restrict__ bsum, int nb) {
    __shared__ int sm[1024];
    int t = threadIdx.x;
    int v = (t < nb) ? bsum[t] : 0;
    sm[t] = v;
    __syncthreads();
    for (int off = 1; off < 1024; off <<= 1) {
        int u = (t >= off) ? sm[t - off] : 0;
        __syncthreads();
        sm[t] += u;
        __syncthreads();
    }
    if (t < nb) bsum[t] = sm[t] - v;  // exclusive
}
__global__ void k_scan3(int* __restrict__ rowptr, int* __restrict__ cursor,
                        const int* __restrict__ bsum, int n, int e) {
    int i = blockIdx.x * 256 + threadIdx.x;
    if (i < n) {
        int v = rowptr[i] + bsum[blockIdx.x];
        rowptr[i] = v;
        cursor[i] = v;
    }
    if (i == 0) rowptr[n] = e;
}
__global__ void k_fill(const int* __restrict__ src, const int* __restrict__ dst,
                       int* __restrict__ cursor, int* __restrict__ csrc, int e) {
    int i = blockIdx.x * blockDim.x + threadIdx.x;
    if (i < e) {
        int d = dst[i];
        int pos = atomicAdd(&cursor[d], 1);
        csrc[pos] = src[i];
    }
}

// ---------------- weight transpose + fp16 convert (both layers) ---------------
__global__ void k_convW(const float* __restrict__ W1, __half* __restrict__ Wt1,
                        const float* __restrict__ W2, __half* __restrict__ Wt2) {
    int idx = blockIdx.x * blockDim.x + threadIdx.x;
    const int n1 = DHID * DIN;
    if (idx < n1) {
        int c = idx / DIN, k = idx % DIN;
        Wt1[idx] = __float2half(W1[(size_t)k * DHID + c]);
    } else if (idx < n1 + DOUT * DIN) {
        int j = idx - n1;
        int c = j / DIN, k = j % DIN;
        Wt2[j] = __float2half(W2[(size_t)k * DOUT + c]);
    }
}

// ------------------- HMMA GEMM (pipelined cp.async A staging) ------------------
// H[row] = half( dinv[row] * ( X[row] @ W ) ),  Wt = [n][k] fp16.
template <int DO, typename TIN>
__global__ void __launch_bounds__(256, 2)
k_gemm_mma(const TIN* __restrict__ X, const __half* __restrict__ Wt,
           const float* __restrict__ dinv, __half* __restrict__ H,
           int n, int ntiles) {
    constexpr int AST = 136;
    constexpr int NT  = DO / 16;
    constexpr int NP  = NT / 2;
    constexpr int KS  = DIN / 16;

    extern __shared__ char sh[];
    __half (*Bs)[AST] = reinterpret_cast<__half(*)[AST]>(sh);
    TIN (*As)[AST] = reinterpret_cast<TIN(*)[AST]>(sh + DO * AST * 2);

    const int tid = threadIdx.x, wid = tid >> 5, lane = tid & 31;
    const int mi = wid & 3, nj = wid >> 2;
    const int n0 = nj * (DO / 2);
    const int g = lane >> 2, c = (lane & 3) * 2;
    const int lrow = lane & 15, lcol = (lane >> 4) * 8;

    auto load_A = [&](int tile, int stage) {
        const int row0 = tile * 64;
        if (sizeof(TIN) == 4) {
            const float* Xf = reinterpret_cast<const float*>(X);
            for (int i = tid; i < 2048; i += 256) {
                int r = i >> 5, kq = (i & 31) * 4;
                int gr = min(row0 + r, n - 1);
                cpasync16(su32(&As[stage * 64 + r][kq]), Xf + (size_t)gr * DIN + kq);
            }
        } else {
            const __half* Xh = reinterpret_cast<const __half*>(X);
            for (int i = tid; i < 1024; i += 256) {
                int r = i >> 4, kq = (i & 15) * 8;
                int gr = min(row0 + r, n - 1);
                cpasync16(su32(&As[stage * 64 + r][kq]), Xh + (size_t)gr * DIN + kq);
            }
        }
    };

    for (int i = tid; i < DO * 16; i += 256) {
        int r = i >> 4, kq = (i & 15) * 8;
        cpasync16(su32(&Bs[r][kq]), Wt + (size_t)r * DIN + kq);
    }
    int tile = blockIdx.x;
    if (tile < ntiles) load_A(tile, 0);
    asm volatile("cp.async.commit_group;");

    unsigned b_base[NP];
#pragma unroll
    for (int p = 0; p < NP; p++) b_base[p] = su32(&Bs[n0 + p * 16 + lrow][lcol]);

    int stage = 0;
    for (; tile < ntiles; tile += gridDim.x, stage ^= 1) {
        const int nxt = tile + gridDim.x;
        if (nxt < ntiles) load_A(nxt, stage ^ 1);
        asm volatile("cp.async.commit_group;");
        asm volatile("cp.async.wait_group 1;");
        __syncthreads();

        float acc[NT][4];
#pragma unroll
        for (int t = 0; t < NT; t++)
#pragma unroll
            for (int q = 0; q < 4; q++) acc[t][q] = 0.f;

        const TIN* arow0 = As[stage * 64 + mi * 16 + g];
        const TIN* arow1 = As[stage * 64 + mi * 16 + g + 8];
        const unsigned a_base = su32(&As[stage * 64 + mi * 16 + lrow][lcol]);

#pragma unroll
        for (int ks = 0; ks < KS; ks++) {
            unsigned a0, a1, a2, a3;
            if (sizeof(TIN) == 4) {
                const int kb = ks * 16 + c;
                const float* f0 = reinterpret_cast<const float*>(arow0);
                const float* f1 = reinterpret_cast<const float*>(arow1);
                float2 x00 = *reinterpret_cast<const float2*>(f0 + kb);
                float2 x10 = *reinterpret_cast<const float2*>(f1 + kb);
                float2 x01 = *reinterpret_cast<const float2*>(f0 + kb + 8);
                float2 x11 = *reinterpret_cast<const float2*>(f1 + kb + 8);
                a0 = packh2(x00.x, x00.y);
                a1 = packh2(x10.x, x10.y);
                a2 = packh2(x01.x, x01.y);
                a3 = packh2(x11.x, x11.y);
            } else {
                ldsm_x4(a_base + ks * 32, a0, a1, a2, a3);
            }
#pragma unroll
            for (int p = 0; p < NP; p++) {
                unsigned b0, b1, b2, b3;
                ldsm_x4(b_base[p] + ks * 32, b0, b1, b2, b3);
                asm volatile(
                    "mma.sync.aligned.m16n8k16.row.col.f32.f16.f16.f32 "
                    "{%0,%1,%2,%3}, {%4,%5,%6,%7}, {%8,%9}, {%0,%1,%2,%3};"
                    : "+f"(acc[2 * p][0]), "+f"(acc[2 * p][1]),
                      "+f"(acc[2 * p][2]), "+f"(acc[2 * p][3])
                    : "r"(a0), "r"(a1), "r"(a2), "r"(a3), "r"(b0), "r"(b2));
                asm volatile(
                    "mma.sync.aligned.m16n8k16.row.col.f32.f16.f16.f32 "
                    "{%0,%1,%2,%3}, {%4,%5,%6,%7}, {%8,%9}, {%0,%1,%2,%3};"
                    : "+f"(acc[2 * p + 1][0]), "+f"(acc[2 * p + 1][1]),
                      "+f"(acc[2 * p + 1][2]), "+f"(acc[2 * p + 1][3])
                    : "r"(a0), "r"(a1), "r"(a2), "r"(a3), "r"(b1), "r"(b3));
            }
        }

        const int r0 = tile * 64 + mi * 16 + g;
        const int r1 = r0 + 8;
        const bool v0 = r0 < n, v1 = r1 < n;
        const float dv0 = v0 ? dinv[r0] : 0.f;
        const float dv1 = v1 ? dinv[r1] : 0.f;
#pragma unroll
        for (int t = 0; t < NT; t++) {
            const int col = n0 + t * 8 + c;
            if (v0) {
                __half2 h0 = __floats2half2_rn(acc[t][0] * dv0, acc[t][1] * dv0);
                *reinterpret_cast<__half2*>(H + (size_t)r0 * DO + col) = h0;
            }
            if (v1) {
                __half2 h1 = __floats2half2_rn(acc[t][2] * dv1, acc[t][3] * dv1);
                *reinterpret_cast<__half2*>(H + (size_t)r1 * DO + col) = h1;
            }
        }
        __syncthreads();
    }
    asm volatile("cp.async.wait_group 0;");
}

// ----------------------------- CSR gather aggregation (fp16 in) --------------
// OUT[d] = f( dinv[d] * ( sum_{s in N(d)} H[s] + H[d] ) + bias )
// HOUT: f = relu, stored fp16 (layer 1).  else: identity, stored fp32 (layer 2).
template <int D, bool HOUT>
__global__ void k_gather(const __half* __restrict__ H, const int* __restrict__ rowptr,
                         const int* __restrict__ csrc, const float* __restrict__ dinv,
                         const float* __restrict__ bias, void* __restrict__ OUTv, int n) {
    constexpr int VW = D / 32;  // halves per lane: 4 or 2
    const int w = (blockIdx.x * blockDim.x + threadIdx.x) >> 5;
    const int lane = threadIdx.x & 31;
    if (w >= n) return;

    const int beg = __ldg(&rowptr[w]);
    const int end = __ldg(&rowptr[w + 1]);

    float accA[VW], accB[VW];
#pragma unroll
    for (int c = 0; c < VW; c++) { accA[c] = 0.f; accB[c] = 0.f; }

    auto addrow = [&](int s, float* acc) {
        const __half* hp = H + (size_t)s * D + lane * VW;
        if (VW == 4) {
            uint2 raw = __ldg(reinterpret_cast<const uint2*>(hp));
            float2 f0 = __half22float2(*reinterpret_cast<__half2*>(&raw.x));
            float2 f1 = __half22float2(*reinterpret_cast<__half2*>(&raw.y));
            acc[0] += f0.x; acc[1] += f0.y; acc[2] += f1.x; acc[3] += f1.y;
        } else {
            unsigned raw = __ldg(reinterpret_cast<const unsigned*>(hp));
            float2 f0 = __half22float2(*reinterpret_cast<__half2*>(&raw));
            acc[0] += f0.x; acc[1] += f0.y;
        }
    };

    int j = beg;
    for (; j + 3 < end; j += 4) {
        int s0 = __ldg(&csrc[j]);
        int s1 = __ldg(&csrc[j + 1]);
        int s2 = __ldg(&csrc[j + 2]);
        int s3 = __ldg(&csrc[j + 3]);
        addrow(s0, accA); addrow(s1, accB);
        addrow(s2, accA); addrow(s3, accB);
    }
    for (; j < end; j++) addrow(__ldg(&csrc[j]), accA);
    addrow(w, accB);  // self loop

    const float dv = __ldg(&dinv[w]);
    float val[VW];
#pragma unroll
    for (int c = 0; c < VW; c++) {
        float bb = __ldg(&bias[lane * VW + c]);
        val[c] = fmaf(accA[c] + accB[c], dv, bb);
        if (HOUT) val[c] = fmaxf(val[c], 0.f);
    }

    if (HOUT) {
        __half* O = reinterpret_cast<__half*>(OUTv) + (size_t)w * D + lane * VW;
        if (VW == 4) {
            uint2 st;
            st.x = packh2(val[0], val[1]);
            st.y = packh2(val[2], val[3]);
            *reinterpret_cast<uint2*>(O) = st;
        } else {
            *reinterpret_cast<__half2*>(O) = __floats2half2_rn(val[0], val[1]);
        }
    } else {
        float* O = reinterpret_cast<float*>(OUTv) + (size_t)w * D + lane * VW;
        if (VW == 4)
            *reinterpret_cast<float4*>(O) = make_float4(val[0], val[1], val[2], val[3]);
        else
            *reinterpret_cast<float2*>(O) = make_float2(val[0], val[1]);
    }
}

// -----------------------------------------------------------------------------
extern "C" void kernel_launch(void* const* d_in, const int* in_sizes, int n_in,
                              void* d_out, int out_size) {
    const float* x  = (const float*)d_in[0];
    const int*   ei = (const int*)d_in[1];  // [2,E]: src=ei, dst=ei+e
    const float* W1 = (const float*)d_in[2];
    const float* b1 = (const float*)d_in[3];
    const float* W2 = (const float*)d_in[4];
    const float* b2 = (const float*)d_in[5];
    float* out = (float*)d_out;

    const int n = in_sizes[0] / DIN;
    const int e = in_sizes[1] / 2;

    __half *h, *aggh, *Wt1, *Wt2;
    float* dinv;
    int *cnt, *rowptr, *cursor, *csrc, *bsum;
    cudaGetSymbolAddress((void**)&h,      g_h);
    cudaGetSymbolAddress((void**)&aggh,   g_agg);
    cudaGetSymbolAddress((void**)&dinv,   g_dinv);
    cudaGetSymbolAddress((void**)&cnt,    g_cnt);
    cudaGetSymbolAddress((void**)&rowptr, g_rowptr);
    cudaGetSymbolAddress((void**)&cursor, g_cursor);
    cudaGetSymbolAddress((void**)&csrc,   g_csrc);
    cudaGetSymbolAddress((void**)&bsum,   g_bsum);
    cudaGetSymbolAddress((void**)&Wt1,    g_Wt1);
    cudaGetSymbolAddress((void**)&Wt2,    g_Wt2);

    // dynamic smem: B (DO x 136 halves) + 2 A stages (64 x 136 TIN)
    const int SM1 = DHID * 136 * 2 + 2 * 64 * 136 * 4;  // 104448
    const int SM2 = DOUT * 136 * 2 + 2 * 64 * 136 * 2;  // 52224
    cudaFuncSetAttribute(k_gemm_mma<DHID, float>,
                         cudaFuncAttributeMaxDynamicSharedMemorySize, SM1);
    cudaFuncSetAttribute(k_gemm_mma<DOUT, __half>,
                         cudaFuncAttributeMaxDynamicSharedMemorySize, SM2);

    const int TB = 256;
    const int nb = (n + TB - 1) / TB;      // scan blocks
    const int ntiles = (n + 63) / 64;      // gemm tiles (64 rows each)
    const int GG = 296;                    // gemm grid (2 blocks/SM)
    const int gemm_grid = ntiles < GG ? ntiles : GG;
    const int ab = (n + 7) / 8;            // gather blocks (8 warps/block)
    const int wtot = DHID * DIN + DOUT * DIN;

    // Fork-join with the CORRECT dependency granularity:
    //   gemm1 needs only dinv  -> waits on eDinv (recorded right after scan1)
    //   gather-1 needs csrc    -> waits on eJoin (end of chain)
    // sB is non-blocking so capture records no false edges vs stream 0.
    // Streams/events created fresh per call (no device memory, capture-legal).
    cudaStream_t sB;
    cudaStreamCreateWithFlags(&sB, cudaStreamNonBlocking);
    cudaEvent_t eFork, eDinv, eJoin;
    cudaEventCreateWithFlags(&eFork, cudaEventDisableTiming);
    cudaEventCreateWithFlags(&eDinv, cudaEventDisableTiming);
    cudaEventCreateWithFlags(&eJoin, cudaEventDisableTiming);

    cudaEventRecord(eFork, 0);
    cudaStreamWaitEvent(sB, eFork, 0);

    // --- stream sB: degree + CSR build ---
    cudaMemsetAsync(cnt, 0, (size_t)n * sizeof(int), sB);
    k_hist<<<(e + TB - 1) / TB, TB, 0, sB>>>(ei + e, cnt, e);
    k_scan1<<<nb, TB, 0, sB>>>(cnt, rowptr, bsum, dinv, n);
    cudaEventRecord(eDinv, sB);            // dinv ready
    k_scan2<<<1, 1024, 0, sB>>>(bsum, nb);
    k_scan3<<<nb, TB, 0, sB>>>(rowptr, cursor, bsum, n, e);
    k_fill<<<(e + TB - 1) / TB, TB, 0, sB>>>(ei, ei + e, cursor, csrc, e);
    cudaEventRecord(eJoin, sB);            // rowptr/csrc ready

    // --- stream 0: weights (overlaps memset/hist), then gemm1 after dinv ---
    k_convW<<<(wtot + TB - 1) / TB, TB>>>(W1, Wt1, W2, Wt2);
    cudaStreamWaitEvent(0, eDinv, 0);
    k_gemm_mma<DHID, float><<<gemm_grid, 256, SM1>>>(x, Wt1, dinv, h, n, ntiles);
    // gemm1 overlaps scan2 + scan3 + fill on sB

    cudaStreamWaitEvent(0, eJoin, 0);
    // layer-1 aggregate (relu + fp16 out), layer-2 GEMM + aggregate
    k_gather<DHID, true><<<ab, 256>>>(h, rowptr, csrc, dinv, b1, aggh, n);
    k_gemm_mma<DOUT, __half><<<gemm_grid, 256, SM2>>>(aggh, Wt2, dinv, h, n, ntiles);
    k_gather<DOUT, false><<<ab, 256>>>(h, rowptr, csrc, dinv, b2, out, n);
}